// round 8
// baseline (speedup 1.0000x reference)
#include <cuda_runtime.h>
#include <math.h>

// Problem constants
#define N_    3072
#define DIM_  3
#define M_    3
#define E_    98304
#define CUM_  36
#define HID_  64
#define OUTD_ 5
#define NK9   (N_ * 9)          // 27648 floats per R row
#define OUT_OFF (N_ * OUTD_)    // 15360 : R starts after `out`

// Scratch (no allocations allowed -> device globals)
__device__ __align__(16) float g_A[N_ * 9];       // x @ W_sheaf[:3] + b_sheaf
__device__ __align__(16) float g_B[N_ * 9];       // x @ W_sheaf[3:]
__device__ __align__(16) float g_feat[N_ * CUM_]; // [h1 (9) | h2 (27)]
__device__ float g_deg[N_];
__device__ __align__(16) float g_agg[N_ * CUM_];

__device__ __forceinline__ float fast_tanh(float v) {
    float r;
    asm("tanh.approx.f32 %0, %1;" : "=f"(r) : "f"(v));
    return r;
}

// ---------------- zero scratch accumulators ----------------
__global__ void k_zero() {
    int i = blockIdx.x * blockDim.x + threadIdx.x;
    if (i < N_ * CUM_) { g_feat[i] = 0.f; g_agg[i] = 0.f; }
    if (i < N_)        g_deg[i] = 0.f;
}

// ---------------- sheaf rank factors A, B ----------------
__global__ void k_ab(const float* __restrict__ x,
                     const float* __restrict__ Ws,
                     const float* __restrict__ bs) {
    int idx = blockIdx.x * blockDim.x + threadIdx.x;
    if (idx >= N_ * 9) return;
    int i = idx / 9, k = idx - 9 * i;
    float x0 = x[i * 3 + 0], x1 = x[i * 3 + 1], x2 = x[i * 3 + 2];
    g_A[idx] = x0 * Ws[k] + x1 * Ws[9 + k] + x2 * Ws[18 + k] + bs[k];
    g_B[idx] = x0 * Ws[27 + k] + x1 * Ws[36 + k] + x2 * Ws[45 + k];
}

// ---------------- R[i,j,:] = tanh(A[i,:] + B[j,:]) ----------------
// grid = (27, 3072): row i = blockIdx.y; each thread does 4 consecutive t.
// 27 blocks * 256 threads * 4 = 27648 = NK9 exactly.
__global__ void k_R(float* __restrict__ Rout) {
    __shared__ float sA[9];
    int i = blockIdx.y;
    if (threadIdx.x < 9) sA[threadIdx.x] = g_A[i * 9 + threadIdx.x];
    __syncthreads();
    int t0 = (blockIdx.x * 256 + threadIdx.x) * 4;
    float4 b = *reinterpret_cast<const float4*>(&g_B[t0]);
    int k0 = t0 % 9;
    int k1 = k0 + 1; if (k1 >= 9) k1 -= 9;
    int k2 = k1 + 1; if (k2 >= 9) k2 -= 9;
    int k3 = k2 + 1; if (k3 >= 9) k3 -= 9;
    float4 r;
    r.x = fast_tanh(sA[k0] + b.x);
    r.y = fast_tanh(sA[k1] + b.y);
    r.z = fast_tanh(sA[k2] + b.z);
    r.w = fast_tanh(sA[k3] + b.w);
    // streaming store: nothing reads R back, don't pollute L2
    __stcs(reinterpret_cast<float4*>(Rout + (size_t)i * NK9 + t0), r);
}

// ---------------- gradient hop 1 (x: 3ch -> 9ch) + degree ----------------
__global__ void k_g1(const float* __restrict__ x,
                     const int* __restrict__ ei,
                     const float* __restrict__ K) {
    int e = blockIdx.x * blockDim.x + threadIdx.x;
    if (e >= E_) return;
    int s = ei[e], t = ei[E_ + e];
    float x0 = x[s * 3 + 0], x1 = x[s * 3 + 1], x2 = x[s * 3 + 2];
    atomicAdd(&g_deg[t], 1.f);
    float* ft = &g_feat[t * CUM_];
#pragma unroll
    for (int k = 0; k < 3; k++) {
        float kv = K[k * E_ + e];
        atomicAdd(ft + k * 3 + 0, kv * x0);
        atomicAdd(ft + k * 3 + 1, kv * x1);
        atomicAdd(ft + k * 3 + 2, kv * x2);
    }
}

// ---------------- gradient hop 2 (h1: 9ch -> 27ch) ----------------
__global__ void k_g2(const int* __restrict__ ei,
                     const float* __restrict__ K) {
    int idx = blockIdx.x * blockDim.x + threadIdx.x;
    if (idx >= E_ * 9) return;
    int e = idx / 9, j = idx - 9 * e;
    int s = ei[e], t = ei[E_ + e];
    float h = g_feat[s * CUM_ + j];
#pragma unroll
    for (int k = 0; k < 3; k++)
        atomicAdd(&g_feat[t * CUM_ + 9 + k * 9 + j], K[k * E_ + e] * h);
}

// ---------------- GCN mean-aggregate (sum part) ----------------
__global__ void k_agg(const int* __restrict__ ei) {
    int idx = blockIdx.x * blockDim.x + threadIdx.x;
    if (idx >= E_ * CUM_) return;
    int e = idx / CUM_, c = idx - CUM_ * e;
    int s = ei[e], t = ei[E_ + e];
    atomicAdd(&g_agg[t * CUM_ + c], g_feat[s * CUM_ + c]);
}

// ---------------- fused head: conv(36->36) + MLP(36->64->5) ----------------
// one block of 64 threads per node; activations staged in smem
__global__ void k_head(const float* __restrict__ Wc, const float* __restrict__ bc,
                       const float* __restrict__ W1, const float* __restrict__ b1,
                       const float* __restrict__ W2, const float* __restrict__ b2,
                       float* __restrict__ out) {
    int i = blockIdx.x;
    int o = threadIdx.x;                 // 0..63
    __shared__ float s_in[CUM_];
    __shared__ float s_conv[CUM_];
    __shared__ float s_hid[HID_];

    float inv = 1.f / fmaxf(g_deg[i], 1.f);
    if (o < CUM_) s_in[o] = g_agg[i * CUM_ + o] * inv;
    __syncthreads();

    if (o < CUM_) {
        float acc = bc[o];
#pragma unroll
        for (int c = 0; c < CUM_; c++) acc += s_in[c] * Wc[c * CUM_ + o];
        s_conv[o] = fmaxf(acc, 0.f);
    }
    __syncthreads();

    {
        float acc = b1[o];
#pragma unroll
        for (int c = 0; c < CUM_; c++) acc += s_conv[c] * W1[c * HID_ + o];
        s_hid[o] = fmaxf(acc, 0.f);
    }
    __syncthreads();

    if (o < OUTD_) {
        float acc = b2[o];
#pragma unroll
        for (int c = 0; c < HID_; c++) acc += s_hid[c] * W2[c * OUTD_ + o];
        out[i * OUTD_ + o] = acc;
    }
}

extern "C" void kernel_launch(void* const* d_in, const int* in_sizes, int n_in,
                              void* d_out, int out_size) {
    const float* x  = (const float*)d_in[0];
    const int*   ei = (const int*)d_in[1];     // int32! (JAX x64 disabled)
    const float* K  = (const float*)d_in[2];
    const float* Ws = (const float*)d_in[3];
    const float* bs = (const float*)d_in[4];
    const float* Wc = (const float*)d_in[5];
    const float* bc = (const float*)d_in[6];
    const float* W1 = (const float*)d_in[7];
    const float* b1 = (const float*)d_in[8];
    const float* W2 = (const float*)d_in[9];
    const float* b2 = (const float*)d_in[10];
    float* out = (float*)d_out;

    k_zero<<<(N_ * CUM_ + 255) / 256, 256>>>();
    k_ab<<<(N_ * 9 + 255) / 256, 256>>>(x, Ws, bs);
    k_R<<<dim3(27, N_), 256>>>(out + OUT_OFF);
    k_g1<<<(E_ + 255) / 256, 256>>>(x, ei, K);
    k_g2<<<(E_ * 9 + 255) / 256, 256>>>(ei, K);
    k_agg<<<(E_ * CUM_ + 255) / 256, 256>>>(ei);
    k_head<<<N_, HID_>>>(Wc, bc, W1, b1, W2, b2, out);
}

// round 9
// speedup vs baseline: 1.0726x; 1.0726x over previous
#include <cuda_runtime.h>
#include <math.h>

// Problem constants
#define N_    3072
#define DIM_  3
#define M_    3
#define E_    98304
#define CUM_  36
#define HID_  64
#define OUTD_ 5
#define NK9   (N_ * 9)          // 27648 floats per R row
#define OUT_OFF (N_ * OUTD_)    // 15360 : R starts after `out`
#define RTILE 8                 // rows of R per block

// Scratch (no allocations allowed -> device globals)
__device__ __align__(16) float g_A[N_ * 9];       // x @ W_sheaf[:3] + b_sheaf
__device__ __align__(16) float g_B[N_ * 9];       // x @ W_sheaf[3:]
__device__ __align__(16) float g_feat[N_ * CUM_]; // [h1 (9) | h2 (27)]
__device__ float g_deg[N_];
__device__ __align__(16) float g_agg[N_ * CUM_];

__device__ __forceinline__ float fast_tanh(float v) {
    float r;
    asm("tanh.approx.f32 %0, %1;" : "=f"(r) : "f"(v));
    return r;
}

// ---------------- zero scratch accumulators ----------------
__global__ void k_zero() {
    int i = blockIdx.x * blockDim.x + threadIdx.x;
    if (i < N_ * CUM_) { g_feat[i] = 0.f; g_agg[i] = 0.f; }
    if (i < N_)        g_deg[i] = 0.f;
}

// ---------------- sheaf rank factors A, B ----------------
__global__ void k_ab(const float* __restrict__ x,
                     const float* __restrict__ Ws,
                     const float* __restrict__ bs) {
    int idx = blockIdx.x * blockDim.x + threadIdx.x;
    if (idx >= N_ * 9) return;
    int i = idx / 9, k = idx - 9 * i;
    float x0 = x[i * 3 + 0], x1 = x[i * 3 + 1], x2 = x[i * 3 + 2];
    g_A[idx] = x0 * Ws[k] + x1 * Ws[9 + k] + x2 * Ws[18 + k] + bs[k];
    g_B[idx] = x0 * Ws[27 + k] + x1 * Ws[36 + k] + x2 * Ws[45 + k];
}

// ---------------- R[i,j,:] = tanh(A[i,:] + B[j,:]) ----------------
// grid = (27, 384). Each block: 8 consecutive rows i, 1024 consecutive t.
// B chunk loaded ONCE into registers, reused across the 8 rows (8x less
// L2 read traffic than row-per-block).
__global__ void k_R(float* __restrict__ Rout) {
    __shared__ float sA[RTILE * 9];
    int tid = threadIdx.x;
    int i0 = blockIdx.y * RTILE;
    if (tid < RTILE * 9) sA[tid] = g_A[i0 * 9 + tid];
    __syncthreads();
    int t0 = (blockIdx.x * 256 + tid) * 4;
    float4 b = *reinterpret_cast<const float4*>(&g_B[t0]);
    int k0 = t0 % 9;
    int k1 = k0 + 1; if (k1 >= 9) k1 -= 9;
    int k2 = k1 + 1; if (k2 >= 9) k2 -= 9;
    int k3 = k2 + 1; if (k3 >= 9) k3 -= 9;
#pragma unroll
    for (int r = 0; r < RTILE; r++) {
        const float* a = &sA[r * 9];
        float4 v;
        v.x = fast_tanh(a[k0] + b.x);
        v.y = fast_tanh(a[k1] + b.y);
        v.z = fast_tanh(a[k2] + b.z);
        v.w = fast_tanh(a[k3] + b.w);
        // streaming store: nothing reads R back, don't pollute L2
        __stcs(reinterpret_cast<float4*>(Rout + (size_t)(i0 + r) * NK9 + t0), v);
    }
}

// ---------------- gradient hop 1 (x: 3ch -> 9ch) + degree ----------------
__global__ void k_g1(const float* __restrict__ x,
                     const int* __restrict__ ei,
                     const float* __restrict__ K) {
    int e = blockIdx.x * blockDim.x + threadIdx.x;
    if (e >= E_) return;
    int s = ei[e], t = ei[E_ + e];
    float x0 = x[s * 3 + 0], x1 = x[s * 3 + 1], x2 = x[s * 3 + 2];
    atomicAdd(&g_deg[t], 1.f);
    float* ft = &g_feat[t * CUM_];
#pragma unroll
    for (int k = 0; k < 3; k++) {
        float kv = K[k * E_ + e];
        atomicAdd(ft + k * 3 + 0, kv * x0);
        atomicAdd(ft + k * 3 + 1, kv * x1);
        atomicAdd(ft + k * 3 + 2, kv * x2);
    }
}

// ---------------- gradient hop 2 (h1: 9ch -> 27ch) ----------------
__global__ void k_g2(const int* __restrict__ ei,
                     const float* __restrict__ K) {
    int idx = blockIdx.x * blockDim.x + threadIdx.x;
    if (idx >= E_ * 9) return;
    int e = idx / 9, j = idx - 9 * e;
    int s = ei[e], t = ei[E_ + e];
    float h = g_feat[s * CUM_ + j];
#pragma unroll
    for (int k = 0; k < 3; k++)
        atomicAdd(&g_feat[t * CUM_ + 9 + k * 9 + j], K[k * E_ + e] * h);
}

// ---------------- GCN mean-aggregate (sum part) ----------------
// thread per (edge, 4-channel group): float4 gather (rows are 144B, 16B-aligned)
__global__ void k_agg(const int* __restrict__ ei) {
    int idx = blockIdx.x * blockDim.x + threadIdx.x;
    if (idx >= E_ * 9) return;
    int e = idx / 9, c4 = idx - 9 * e;
    int s = ei[e], t = ei[E_ + e];
    float4 v = *reinterpret_cast<const float4*>(&g_feat[s * CUM_ + c4 * 4]);
    float* dst = &g_agg[t * CUM_ + c4 * 4];
    atomicAdd(dst + 0, v.x);
    atomicAdd(dst + 1, v.y);
    atomicAdd(dst + 2, v.z);
    atomicAdd(dst + 3, v.w);
}

// ---------------- fused head: conv(36->36) + MLP(36->64->5) ----------------
__global__ void k_head(const float* __restrict__ Wc, const float* __restrict__ bc,
                       const float* __restrict__ W1, const float* __restrict__ b1,
                       const float* __restrict__ W2, const float* __restrict__ b2,
                       float* __restrict__ out) {
    int i = blockIdx.x;
    int o = threadIdx.x;                 // 0..63
    __shared__ float s_in[CUM_];
    __shared__ float s_conv[CUM_];
    __shared__ float s_hid[HID_];

    float inv = 1.f / fmaxf(g_deg[i], 1.f);
    if (o < CUM_) s_in[o] = g_agg[i * CUM_ + o] * inv;
    __syncthreads();

    if (o < CUM_) {
        float acc = bc[o];
#pragma unroll
        for (int c = 0; c < CUM_; c++) acc += s_in[c] * Wc[c * CUM_ + o];
        s_conv[o] = fmaxf(acc, 0.f);
    }
    __syncthreads();

    {
        float acc = b1[o];
#pragma unroll
        for (int c = 0; c < CUM_; c++) acc += s_conv[c] * W1[c * HID_ + o];
        s_hid[o] = fmaxf(acc, 0.f);
    }
    __syncthreads();

    if (o < OUTD_) {
        float acc = b2[o];
#pragma unroll
        for (int c = 0; c < HID_; c++) acc += s_hid[c] * W2[c * OUTD_ + o];
        out[i * OUTD_ + o] = acc;
    }
}

extern "C" void kernel_launch(void* const* d_in, const int* in_sizes, int n_in,
                              void* d_out, int out_size) {
    const float* x  = (const float*)d_in[0];
    const int*   ei = (const int*)d_in[1];     // int32 (JAX x64 disabled)
    const float* K  = (const float*)d_in[2];
    const float* Ws = (const float*)d_in[3];
    const float* bs = (const float*)d_in[4];
    const float* Wc = (const float*)d_in[5];
    const float* bc = (const float*)d_in[6];
    const float* W1 = (const float*)d_in[7];
    const float* b1 = (const float*)d_in[8];
    const float* W2 = (const float*)d_in[9];
    const float* b2 = (const float*)d_in[10];
    float* out = (float*)d_out;

    // side stream + fork/join events (host-side objects only; created per
    // call — kernel_launch runs only a handful of times, replays use the graph)
    cudaStream_t s1;
    cudaStreamCreateWithFlags(&s1, cudaStreamNonBlocking);
    cudaEvent_t evF, evJ;
    cudaEventCreateWithFlags(&evF, cudaEventDisableTiming);
    cudaEventCreateWithFlags(&evJ, cudaEventDisableTiming);

    k_zero<<<(N_ * CUM_ + 255) / 256, 256>>>();
    k_ab<<<(N_ * 9 + 255) / 256, 256>>>(x, Ws, bs);

    // fork: R tensor on side stream, overlapped with the scatter chain
    cudaEventRecord(evF, 0);
    cudaStreamWaitEvent(s1, evF, 0);
    k_R<<<dim3(27, N_ / RTILE), 256, 0, s1>>>(out + OUT_OFF);

    k_g1<<<(E_ + 255) / 256, 256>>>(x, ei, K);
    k_g2<<<(E_ * 9 + 255) / 256, 256>>>(ei, K);
    k_agg<<<(E_ * 9 + 255) / 256, 256>>>(ei);
    k_head<<<N_, HID_>>>(Wc, bc, W1, b1, W2, b2, out);

    // join: harness reads d_out after this stream completes
    cudaEventRecord(evJ, s1);
    cudaStreamWaitEvent(0, evJ, 0);
}

// round 12
// speedup vs baseline: 1.0999x; 1.0254x over previous
#include <cuda_runtime.h>
#include <math.h>

// Problem constants
#define N_    3072
#define DIM_  3
#define M_    3
#define E_    98304
#define CUM_  36
#define HID_  64
#define OUTD_ 5
#define NK9   (N_ * 9)          // 27648 floats per R row
#define OUT_OFF (N_ * OUTD_)    // 15360 : R starts after `out`
#define RTILE 8                 // rows of R per block

// Scratch (no allocations allowed -> device globals)
__device__ __align__(16) float g_A[N_ * 9];       // x @ W_sheaf[:3] + b_sheaf
__device__ __align__(16) float g_B[N_ * 9];       // x @ W_sheaf[3:]
__device__ __align__(16) float g_feat[N_ * CUM_]; // [h1 (9) | h2 (27)]
__device__ float g_deg[N_];
__device__ __align__(16) float g_agg[N_ * CUM_];

__device__ __forceinline__ float fast_tanh(float v) {
    float r;
    asm("tanh.approx.f32 %0, %1;" : "=f"(r) : "f"(v));
    return r;
}

// ---------------- zero scratch accumulators ----------------
__global__ void k_zero() {
    int i = blockIdx.x * blockDim.x + threadIdx.x;
    if (i < N_ * CUM_) { g_feat[i] = 0.f; g_agg[i] = 0.f; }
    if (i < N_)        g_deg[i] = 0.f;
}

// ---------------- sheaf rank factors A, B ----------------
__global__ void k_ab(const float* __restrict__ x,
                     const float* __restrict__ Ws,
                     const float* __restrict__ bs) {
    int idx = blockIdx.x * blockDim.x + threadIdx.x;
    if (idx >= N_ * 9) return;
    int i = idx / 9, k = idx - 9 * i;
    float x0 = x[i * 3 + 0], x1 = x[i * 3 + 1], x2 = x[i * 3 + 2];
    g_A[idx] = x0 * Ws[k] + x1 * Ws[9 + k] + x2 * Ws[18 + k] + bs[k];
    g_B[idx] = x0 * Ws[27 + k] + x1 * Ws[36 + k] + x2 * Ws[45 + k];
}

// ---------------- R[i,j,:] = tanh(A[i,:] + B[j,:]) ----------------
// grid = (27, 384). Each block: 8 consecutive rows i, 1024 consecutive t.
// B chunk loaded ONCE into registers, reused across the 8 rows.
__global__ void k_R(float* __restrict__ Rout) {
    __shared__ float sA[RTILE * 9];
    int tid = threadIdx.x;
    int i0 = blockIdx.y * RTILE;
    if (tid < RTILE * 9) sA[tid] = g_A[i0 * 9 + tid];
    __syncthreads();
    int t0 = (blockIdx.x * 256 + tid) * 4;
    float4 b = *reinterpret_cast<const float4*>(&g_B[t0]);
    int k0 = t0 % 9;
    int k1 = k0 + 1; if (k1 >= 9) k1 -= 9;
    int k2 = k1 + 1; if (k2 >= 9) k2 -= 9;
    int k3 = k2 + 1; if (k3 >= 9) k3 -= 9;
#pragma unroll
    for (int r = 0; r < RTILE; r++) {
        const float* a = &sA[r * 9];
        float4 v;
        v.x = fast_tanh(a[k0] + b.x);
        v.y = fast_tanh(a[k1] + b.y);
        v.z = fast_tanh(a[k2] + b.z);
        v.w = fast_tanh(a[k3] + b.w);
        // streaming store: nothing reads R back, don't pollute L2
        __stcs(reinterpret_cast<float4*>(Rout + (size_t)(i0 + r) * NK9 + t0), v);
    }
}

// ---------------- gradient hop 1 (x: 3ch -> 9ch) + degree ----------------
// one thread per (edge, kernel k): 3x the warps of the per-edge version,
// shorter dependency chain -> hides gather latency better
__global__ void k_g1(const float* __restrict__ x,
                     const int* __restrict__ ei,
                     const float* __restrict__ K) {
    int idx = blockIdx.x * blockDim.x + threadIdx.x;
    if (idx >= 3 * E_) return;
    int k = idx / E_, e = idx - k * E_;      // consecutive threads: same k, consecutive e
    int s = ei[e], t = ei[E_ + e];
    float kv = K[k * E_ + e];
    if (k == 0) atomicAdd(&g_deg[t], 1.f);
    float x0 = x[s * 3 + 0], x1 = x[s * 3 + 1], x2 = x[s * 3 + 2];
    float* ft = &g_feat[t * CUM_ + k * 3];
    atomicAdd(ft + 0, kv * x0);
    atomicAdd(ft + 1, kv * x1);
    atomicAdd(ft + 2, kv * x2);
}

// ---------------- gradient hop 2 (h1: 9ch -> 27ch) ----------------
__global__ void k_g2(const int* __restrict__ ei,
                     const float* __restrict__ K) {
    int idx = blockIdx.x * blockDim.x + threadIdx.x;
    if (idx >= E_ * 9) return;
    int e = idx / 9, j = idx - 9 * e;
    int s = ei[e], t = ei[E_ + e];
    float h = g_feat[s * CUM_ + j];
#pragma unroll
    for (int k = 0; k < 3; k++)
        atomicAdd(&g_feat[t * CUM_ + 9 + k * 9 + j], K[k * E_ + e] * h);
}

// ---------------- GCN mean-aggregate (sum part) ----------------
// thread per (edge, 4-channel group): float4 gather (rows are 144B, 16B-aligned)
__global__ void k_agg(const int* __restrict__ ei) {
    int idx = blockIdx.x * blockDim.x + threadIdx.x;
    if (idx >= E_ * 9) return;
    int e = idx / 9, c4 = idx - 9 * e;
    int s = ei[e], t = ei[E_ + e];
    float4 v = *reinterpret_cast<const float4*>(&g_feat[s * CUM_ + c4 * 4]);
    float* dst = &g_agg[t * CUM_ + c4 * 4];
    atomicAdd(dst + 0, v.x);
    atomicAdd(dst + 1, v.y);
    atomicAdd(dst + 2, v.z);
    atomicAdd(dst + 3, v.w);
}

// ---------------- fused head: conv(36->36) + MLP(36->64->5) ----------------
__global__ void k_head(const float* __restrict__ Wc, const float* __restrict__ bc,
                       const float* __restrict__ W1, const float* __restrict__ b1,
                       const float* __restrict__ W2, const float* __restrict__ b2,
                       float* __restrict__ out) {
    int i = blockIdx.x;
    int o = threadIdx.x;                 // 0..63
    __shared__ float s_in[CUM_];
    __shared__ float s_conv[CUM_];
    __shared__ float s_hid[HID_];

    float inv = 1.f / fmaxf(g_deg[i], 1.f);
    if (o < CUM_) s_in[o] = g_agg[i * CUM_ + o] * inv;
    __syncthreads();

    if (o < CUM_) {
        float acc = bc[o];
#pragma unroll
        for (int c = 0; c < CUM_; c++) acc += s_in[c] * Wc[c * CUM_ + o];
        s_conv[o] = fmaxf(acc, 0.f);
    }
    __syncthreads();

    {
        float acc = b1[o];
#pragma unroll
        for (int c = 0; c < CUM_; c++) acc += s_conv[c] * W1[c * HID_ + o];
        s_hid[o] = fmaxf(acc, 0.f);
    }
    __syncthreads();

    if (o < OUTD_) {
        float acc = b2[o];
#pragma unroll
        for (int c = 0; c < HID_; c++) acc += s_hid[c] * W2[c * OUTD_ + o];
        out[i * OUTD_ + o] = acc;
    }
}

extern "C" void kernel_launch(void* const* d_in, const int* in_sizes, int n_in,
                              void* d_out, int out_size) {
    const float* x  = (const float*)d_in[0];
    const int*   ei = (const int*)d_in[1];     // int32 (JAX x64 disabled)
    const float* K  = (const float*)d_in[2];
    const float* Ws = (const float*)d_in[3];
    const float* bs = (const float*)d_in[4];
    const float* Wc = (const float*)d_in[5];
    const float* bc = (const float*)d_in[6];
    const float* W1 = (const float*)d_in[7];
    const float* b1 = (const float*)d_in[8];
    const float* W2 = (const float*)d_in[9];
    const float* b2 = (const float*)d_in[10];
    float* out = (float*)d_out;

    // High-priority side stream for the latency-bound scatter chain so its
    // warps get issue slots while k_R floods the machine with stores.
    // Created once; identical stream ops are issued on every call, so each
    // call (and the captured graph) does the same work.
    static cudaStream_t s1 = nullptr;
    static cudaEvent_t evF = nullptr, evJ = nullptr;
    if (!s1) {
        int prLo, prHi;
        cudaDeviceGetStreamPriorityRange(&prLo, &prHi);
        cudaStreamCreateWithPriority(&s1, cudaStreamNonBlocking, prHi);
        cudaEventCreateWithFlags(&evF, cudaEventDisableTiming);
        cudaEventCreateWithFlags(&evJ, cudaEventDisableTiming);
    }

    // fork immediately: the two branches share NO data
    cudaEventRecord(evF, 0);
    cudaStreamWaitEvent(s1, evF, 0);

    // branch B (high-prio): scatter chain -> head
    k_zero<<<(N_ * CUM_ + 255) / 256, 256, 0, s1>>>();
    k_g1<<<(3 * E_ + 255) / 256, 256, 0, s1>>>(x, ei, K);
    k_g2<<<(E_ * 9 + 255) / 256, 256, 0, s1>>>(ei, K);
    k_agg<<<(E_ * 9 + 255) / 256, 256, 0, s1>>>(ei);
    k_head<<<N_, HID_, 0, s1>>>(Wc, bc, W1, b1, W2, b2, out);

    // branch A (main): sheaf factors -> R tensor (DRAM-write-bound)
    k_ab<<<(N_ * 9 + 255) / 256, 256>>>(x, Ws, bs);
    k_R<<<dim3(27, N_ / RTILE), 256>>>(out + OUT_OFF);

    // join: main stream waits for chain
    cudaEventRecord(evJ, s1);
    cudaStreamWaitEvent(0, evJ, 0);
}

// round 13
// speedup vs baseline: 1.2225x; 1.1114x over previous
#include <cuda_runtime.h>
#include <math.h>

// Problem constants
#define N_    3072
#define DIM_  3
#define M_    3
#define E_    98304
#define CUM_  36
#define HID_  64
#define OUTD_ 5
#define NK9   (N_ * 9)          // 27648 floats per R row
#define OUT_OFF (N_ * OUTD_)    // 15360 : R starts after `out`
#define RTILE 8                 // rows of R per block
#define RB_TOTAL 10368          // (27 t-tiles) * (384 row-groups)
#define RB_CHUNK 3456           // RB_TOTAL / 3

// Scratch (no allocations allowed -> device globals)
__device__ __align__(16) float g_A[N_ * 9];
__device__ __align__(16) float g_B[N_ * 9];
__device__ __align__(16) float g_feat[N_ * CUM_]; // [h1 (9) | h2 (27)]
__device__ float g_deg[N_];
__device__ __align__(16) float g_agg[N_ * CUM_];

__device__ __forceinline__ float fast_tanh(float v) {
    float r;
    asm("tanh.approx.f32 %0, %1;" : "=f"(r) : "f"(v));
    return r;
}

// ---------------- R block body: rb in [0, RB_TOTAL) ----------------
// rb % 27 selects the 1024-float t-tile, rb / 27 the 8-row group.
__device__ __forceinline__ void r_body(int rb, float* __restrict__ Rout) {
    __shared__ float sA[RTILE * 9];
    int tid = threadIdx.x;
    int tcol = rb % 27;
    int i0 = (rb / 27) * RTILE;
    if (tid < RTILE * 9) sA[tid] = g_A[i0 * 9 + tid];
    __syncthreads();
    int t0 = (tcol * 256 + tid) * 4;
    float4 b = *reinterpret_cast<const float4*>(&g_B[t0]);
    int k0 = t0 % 9;
    int k1 = k0 + 1; if (k1 >= 9) k1 -= 9;
    int k2 = k1 + 1; if (k2 >= 9) k2 -= 9;
    int k3 = k2 + 1; if (k3 >= 9) k3 -= 9;
#pragma unroll
    for (int r = 0; r < RTILE; r++) {
        const float* a = &sA[r * 9];
        float4 v;
        v.x = fast_tanh(a[k0] + b.x);
        v.y = fast_tanh(a[k1] + b.y);
        v.z = fast_tanh(a[k2] + b.z);
        v.w = fast_tanh(a[k3] + b.w);
        __stcs(reinterpret_cast<float4*>(Rout + (size_t)(i0 + r) * NK9 + t0), v);
    }
}

// ---------------- k0: zero accumulators || sheaf factors A,B ----------------
// blocks [0,432): zero; blocks [432,540): ab
__global__ void k0_init(const float* __restrict__ x,
                        const float* __restrict__ Ws,
                        const float* __restrict__ bs) {
    int bid = blockIdx.x;
    if (bid < 432) {
        int i = bid * 256 + threadIdx.x;          // < N*36 exactly
        g_feat[i] = 0.f; g_agg[i] = 0.f;
        if (i < N_) g_deg[i] = 0.f;
    } else {
        int idx = (bid - 432) * 256 + threadIdx.x; // < N*9 exactly
        int i = idx / 9, k = idx - 9 * i;
        float x0 = x[i * 3 + 0], x1 = x[i * 3 + 1], x2 = x[i * 3 + 2];
        g_A[idx] = x0 * Ws[k] + x1 * Ws[9 + k] + x2 * Ws[18 + k] + bs[k];
        g_B[idx] = x0 * Ws[27 + k] + x1 * Ws[36 + k] + x2 * Ws[45 + k];
    }
}

// ---------------- k1: g1 (1152 blocks) || R chunk 0 (3456), 1:3 ----------------
__global__ void k1_g1_R(const float* __restrict__ x,
                        const int* __restrict__ ei,
                        const float* __restrict__ K,
                        float* __restrict__ Rout) {
    int bid = blockIdx.x;                 // 4608 blocks
    if ((bid & 3) == 0) {
        // gradient hop 1: thread per (edge, kernel k); 1152*256 = 3E exact
        int idx = (bid >> 2) * 256 + threadIdx.x;
        int k = idx / E_, e = idx - k * E_;
        int s = ei[e], t = ei[E_ + e];
        float kv = K[k * E_ + e];
        if (k == 0) atomicAdd(&g_deg[t], 1.f);
        float x0 = x[s * 3 + 0], x1 = x[s * 3 + 1], x2 = x[s * 3 + 2];
        float* ft = &g_feat[t * CUM_ + k * 3];
        atomicAdd(ft + 0, kv * x0);
        atomicAdd(ft + 1, kv * x1);
        atomicAdd(ft + 2, kv * x2);
    } else {
        r_body(bid - (bid >> 2) - 1, Rout);         // rb in [0, 3456)
    }
}

// ---------------- k2: g2 (3456) || R chunk 1 (3456), 1:1 ----------------
__global__ void k2_g2_R(const int* __restrict__ ei,
                        const float* __restrict__ K,
                        float* __restrict__ Rout) {
    int bid = blockIdx.x;                 // 6912 blocks
    if ((bid & 1) == 0) {
        // gradient hop 2: thread per (edge, j); 3456*256 = 9E exact
        int idx = (bid >> 1) * 256 + threadIdx.x;
        int e = idx / 9, j = idx - 9 * e;
        int s = ei[e], t = ei[E_ + e];
        float h = g_feat[s * CUM_ + j];
#pragma unroll
        for (int k = 0; k < 3; k++)
            atomicAdd(&g_feat[t * CUM_ + 9 + k * 9 + j], K[k * E_ + e] * h);
    } else {
        r_body(RB_CHUNK + (bid >> 1), Rout);        // rb in [3456, 6912)
    }
}

// ---------------- k3: agg (3456) || R chunk 2 (3456), 1:1 ----------------
__global__ void k3_agg_R(const int* __restrict__ ei,
                         float* __restrict__ Rout) {
    int bid = blockIdx.x;                 // 6912 blocks
    if ((bid & 1) == 0) {
        // mean-aggregate (sum): thread per (edge, 4ch group); 3456*256 = 9E exact
        int idx = (bid >> 1) * 256 + threadIdx.x;
        int e = idx / 9, c4 = idx - 9 * e;
        int s = ei[e], t = ei[E_ + e];
        float4 v = *reinterpret_cast<const float4*>(&g_feat[s * CUM_ + c4 * 4]);
        float* dst = &g_agg[t * CUM_ + c4 * 4];
        atomicAdd(dst + 0, v.x);
        atomicAdd(dst + 1, v.y);
        atomicAdd(dst + 2, v.z);
        atomicAdd(dst + 3, v.w);
    } else {
        r_body(2 * RB_CHUNK + (bid >> 1), Rout);    // rb in [6912, 10368)
    }
}

// ---------------- k4: fused head conv(36->36)+MLP(36->64->5) ----------------
__global__ void k_head(const float* __restrict__ Wc, const float* __restrict__ bc,
                       const float* __restrict__ W1, const float* __restrict__ b1,
                       const float* __restrict__ W2, const float* __restrict__ b2,
                       float* __restrict__ out) {
    int i = blockIdx.x;
    int o = threadIdx.x;                 // 0..63
    __shared__ float s_in[CUM_];
    __shared__ float s_conv[CUM_];
    __shared__ float s_hid[HID_];

    float inv = 1.f / fmaxf(g_deg[i], 1.f);
    if (o < CUM_) s_in[o] = g_agg[i * CUM_ + o] * inv;
    __syncthreads();

    if (o < CUM_) {
        float acc = bc[o];
#pragma unroll
        for (int c = 0; c < CUM_; c++) acc += s_in[c] * Wc[c * CUM_ + o];
        s_conv[o] = fmaxf(acc, 0.f);
    }
    __syncthreads();

    {
        float acc = b1[o];
#pragma unroll
        for (int c = 0; c < CUM_; c++) acc += s_conv[c] * W1[c * HID_ + o];
        s_hid[o] = fmaxf(acc, 0.f);
    }
    __syncthreads();

    if (o < OUTD_) {
        float acc = b2[o];
#pragma unroll
        for (int c = 0; c < HID_; c++) acc += s_hid[c] * W2[c * OUTD_ + o];
        out[i * OUTD_ + o] = acc;
    }
}

extern "C" void kernel_launch(void* const* d_in, const int* in_sizes, int n_in,
                              void* d_out, int out_size) {
    const float* x  = (const float*)d_in[0];
    const int*   ei = (const int*)d_in[1];     // int32 (JAX x64 disabled)
    const float* K  = (const float*)d_in[2];
    const float* Ws = (const float*)d_in[3];
    const float* bs = (const float*)d_in[4];
    const float* Wc = (const float*)d_in[5];
    const float* bc = (const float*)d_in[6];
    const float* W1 = (const float*)d_in[7];
    const float* b1 = (const float*)d_in[8];
    const float* W2 = (const float*)d_in[9];
    const float* b2 = (const float*)d_in[10];
    float* out = (float*)d_out;
    float* R   = out + OUT_OFF;

    k0_init<<<540, 256>>>(x, Ws, bs);
    k1_g1_R<<<4608, 256>>>(x, ei, K, R);
    k2_g2_R<<<6912, 256>>>(ei, K, R);
    k3_agg_R<<<6912, 256>>>(ei, R);
    k_head<<<N_, HID_>>>(Wc, bc, W1, b1, W2, b2, out);
}

// round 14
// speedup vs baseline: 1.3284x; 1.0867x over previous
#include <cuda_runtime.h>
#include <math.h>

// Problem constants
#define N_    3072
#define DIM_  3
#define M_    3
#define E_    98304
#define CUM_  36
#define HID_  64
#define OUTD_ 5
#define NK9   (N_ * 9)          // 27648 floats per R row
#define OUT_OFF (N_ * OUTD_)    // 15360 : R starts after `out`
#define RTILE 8                 // rows of R per block
#define RB_TOTAL 10368          // (27 t-tiles) * (384 row-groups)
#define RB_CHUNK 3456           // RB_TOTAL / 3

// Scratch (no allocations allowed -> device globals)
__device__ __align__(16) float g_A[N_ * 9];
__device__ __align__(16) float g_B[N_ * 9];
__device__ __align__(16) float g_feat[N_ * CUM_]; // [h1 (9) | h2 (27)]
__device__ float g_deg[N_];
__device__ __align__(16) float g_agg[N_ * CUM_];

__device__ __forceinline__ float fast_tanh(float v) {
    float r;
    asm("tanh.approx.f32 %0, %1;" : "=f"(r) : "f"(v));
    return r;
}

// vector reduction: one RED.128 instead of 4 scalar REDs (sm_90+)
__device__ __forceinline__ void red_add_v4(float* ptr, float4 v) {
    asm volatile("red.global.add.v4.f32 [%0], {%1, %2, %3, %4};"
                 :: "l"(ptr), "f"(v.x), "f"(v.y), "f"(v.z), "f"(v.w)
                 : "memory");
}

// ---------------- R block body: rb in [0, RB_TOTAL) ----------------
// rb % 27 selects the 1024-float t-tile, rb / 27 the 8-row group.
__device__ __forceinline__ void r_body(int rb, float* __restrict__ Rout) {
    __shared__ float sA[RTILE * 9];
    int tid = threadIdx.x;
    int tcol = rb % 27;
    int i0 = (rb / 27) * RTILE;
    if (tid < RTILE * 9) sA[tid] = g_A[i0 * 9 + tid];
    __syncthreads();
    int t0 = (tcol * 256 + tid) * 4;
    float4 b = *reinterpret_cast<const float4*>(&g_B[t0]);
    int k0 = t0 % 9;
    int k1 = k0 + 1; if (k1 >= 9) k1 -= 9;
    int k2 = k1 + 1; if (k2 >= 9) k2 -= 9;
    int k3 = k2 + 1; if (k3 >= 9) k3 -= 9;
#pragma unroll
    for (int r = 0; r < RTILE; r++) {
        const float* a = &sA[r * 9];
        float4 v;
        v.x = fast_tanh(a[k0] + b.x);
        v.y = fast_tanh(a[k1] + b.y);
        v.z = fast_tanh(a[k2] + b.z);
        v.w = fast_tanh(a[k3] + b.w);
        __stcs(reinterpret_cast<float4*>(Rout + (size_t)(i0 + r) * NK9 + t0), v);
    }
}

// ---------------- k0: zero accumulators || sheaf factors A,B ----------------
// blocks [0,432): zero; blocks [432,540): ab
__global__ void k0_init(const float* __restrict__ x,
                        const float* __restrict__ Ws,
                        const float* __restrict__ bs) {
    int bid = blockIdx.x;
    if (bid < 432) {
        int i = bid * 256 + threadIdx.x;          // < N*36 exactly
        g_feat[i] = 0.f; g_agg[i] = 0.f;
        if (i < N_) g_deg[i] = 0.f;
    } else {
        int idx = (bid - 432) * 256 + threadIdx.x; // < N*9 exactly
        int i = idx / 9, k = idx - 9 * i;
        float x0 = x[i * 3 + 0], x1 = x[i * 3 + 1], x2 = x[i * 3 + 2];
        g_A[idx] = x0 * Ws[k] + x1 * Ws[9 + k] + x2 * Ws[18 + k] + bs[k];
        g_B[idx] = x0 * Ws[27 + k] + x1 * Ws[36 + k] + x2 * Ws[45 + k];
    }
}

// ---------------- k1: g1 (1152 blocks) || R chunk 0 (3456), 1:3 ----------------
__global__ void k1_g1_R(const float* __restrict__ x,
                        const int* __restrict__ ei,
                        const float* __restrict__ K,
                        float* __restrict__ Rout) {
    int bid = blockIdx.x;                 // 4608 blocks
    if ((bid & 3) == 0) {
        // gradient hop 1: thread per (edge, kernel k); 1152*256 = 3E exact
        int idx = (bid >> 2) * 256 + threadIdx.x;
        int k = idx / E_, e = idx - k * E_;
        int s = ei[e], t = ei[E_ + e];
        float kv = K[k * E_ + e];
        if (k == 0) atomicAdd(&g_deg[t], 1.f);
        float x0 = x[s * 3 + 0], x1 = x[s * 3 + 1], x2 = x[s * 3 + 2];
        float* ft = &g_feat[t * CUM_ + k * 3];
        atomicAdd(ft + 0, kv * x0);
        atomicAdd(ft + 1, kv * x1);
        atomicAdd(ft + 2, kv * x2);
    } else {
        r_body(bid - (bid >> 2) - 1, Rout);         // rb in [0, 3456)
    }
}

// ---------------- k2: g2 (3456) || R chunk 1 (3456), 1:1 ----------------
__global__ void k2_g2_R(const int* __restrict__ ei,
                        const float* __restrict__ K,
                        float* __restrict__ Rout) {
    int bid = blockIdx.x;                 // 6912 blocks
    if ((bid & 1) == 0) {
        // gradient hop 2: thread per (edge, j); 3456*256 = 9E exact
        int idx = (bid >> 1) * 256 + threadIdx.x;
        int e = idx / 9, j = idx - 9 * e;
        int s = ei[e], t = ei[E_ + e];
        float h = g_feat[s * CUM_ + j];
#pragma unroll
        for (int k = 0; k < 3; k++)
            atomicAdd(&g_feat[t * CUM_ + 9 + k * 9 + j], K[k * E_ + e] * h);
    } else {
        r_body(RB_CHUNK + (bid >> 1), Rout);        // rb in [3456, 6912)
    }
}

// ---------------- k3: agg (3456) || R chunk 2 (3456), 1:1 ----------------
__global__ void k3_agg_R(const int* __restrict__ ei,
                         float* __restrict__ Rout) {
    int bid = blockIdx.x;                 // 6912 blocks
    if ((bid & 1) == 0) {
        // mean-aggregate (sum): thread per (edge, 4ch group); 3456*256 = 9E exact
        // one LDG.128 + one RED.128 per thread (g_agg rows are 144B -> every
        // 16-byte group is 16B-aligned)
        int idx = (bid >> 1) * 256 + threadIdx.x;
        int e = idx / 9, c4 = idx - 9 * e;
        int s = ei[e], t = ei[E_ + e];
        float4 v = *reinterpret_cast<const float4*>(&g_feat[s * CUM_ + c4 * 4]);
        red_add_v4(&g_agg[t * CUM_ + c4 * 4], v);
    } else {
        r_body(2 * RB_CHUNK + (bid >> 1), Rout);    // rb in [6912, 10368)
    }
}

// ---------------- k4: fused head conv(36->36)+MLP(36->64->5) ----------------
__global__ void k_head(const float* __restrict__ Wc, const float* __restrict__ bc,
                       const float* __restrict__ W1, const float* __restrict__ b1,
                       const float* __restrict__ W2, const float* __restrict__ b2,
                       float* __restrict__ out) {
    int i = blockIdx.x;
    int o = threadIdx.x;                 // 0..63
    __shared__ float s_in[CUM_];
    __shared__ float s_conv[CUM_];
    __shared__ float s_hid[HID_];

    float inv = 1.f / fmaxf(g_deg[i], 1.f);
    if (o < CUM_) s_in[o] = g_agg[i * CUM_ + o] * inv;
    __syncthreads();

    if (o < CUM_) {
        float acc = bc[o];
#pragma unroll
        for (int c = 0; c < CUM_; c++) acc += s_in[c] * Wc[c * CUM_ + o];
        s_conv[o] = fmaxf(acc, 0.f);
    }
    __syncthreads();

    {
        float acc = b1[o];
#pragma unroll
        for (int c = 0; c < CUM_; c++) acc += s_conv[c] * W1[c * HID_ + o];
        s_hid[o] = fmaxf(acc, 0.f);
    }
    __syncthreads();

    if (o < OUTD_) {
        float acc = b2[o];
#pragma unroll
        for (int c = 0; c < HID_; c++) acc += s_hid[c] * W2[c * OUTD_ + o];
        out[i * OUTD_ + o] = acc;
    }
}

extern "C" void kernel_launch(void* const* d_in, const int* in_sizes, int n_in,
                              void* d_out, int out_size) {
    const float* x  = (const float*)d_in[0];
    const int*   ei = (const int*)d_in[1];     // int32 (JAX x64 disabled)
    const float* K  = (const float*)d_in[2];
    const float* Ws = (const float*)d_in[3];
    const float* bs = (const float*)d_in[4];
    const float* Wc = (const float*)d_in[5];
    const float* bc = (const float*)d_in[6];
    const float* W1 = (const float*)d_in[7];
    const float* b1 = (const float*)d_in[8];
    const float* W2 = (const float*)d_in[9];
    const float* b2 = (const float*)d_in[10];
    float* out = (float*)d_out;
    float* R   = out + OUT_OFF;

    k0_init<<<540, 256>>>(x, Ws, bs);
    k1_g1_R<<<4608, 256>>>(x, ei, K, R);
    k2_g2_R<<<6912, 256>>>(ei, K, R);
    k3_agg_R<<<6912, 256>>>(ei, R);
    k_head<<<N_, HID_>>>(Wc, bc, W1, b1, W2, b2, out);
}